// round 6
// baseline (speedup 1.0000x reference)
#include <cuda_runtime.h>
#include <cstdint>
#include <math.h>
#include <float.h>

// Problem constants
#define B_   16
#define C_   256
#define HW_  1024
#define N_   16384
#define K_   8192
#define NC_  4194304

// Output layout
#define OFF_Q    0
#define OFF_IDX  4194304
#define OFF_P    4210688
#define OFF_LVQ  4210689
#define OFF_LC   4210690

#define NBLOCKS   128    // N_/128
#define QBLOCKS   64     // K_/128
#define NG        512    // QBLOCKS*8
#define STAGE_BYTES 32768
#define SMEM_MAIN   131072   // 4 stages
#define MARGIN    0.25f

// Scratch: fragment-ordered tf32 operands (hi only)
__device__ float4 g_Ah[NBLOCKS * 8 * 1024];
__device__ float2 g_Bh[QBLOCKS * 8 * 2048];
__device__ float  g_cn2[K_];
__device__ int    g_counts[K_];
__device__ int    g_indices[N_];
__device__ int    g_flag[N_];
__device__ float  g_partials[512];

// ---------------------------------------------------------------------------
__device__ __forceinline__ uint32_t smem_u32(const void* p) {
    uint32_t a;
    asm("{ .reg .u64 t; cvta.to.shared.u64 t, %1; cvt.u32.u64 %0, t; }" : "=r"(a) : "l"(p));
    return a;
}
__device__ __forceinline__ float tf32_rn(float x) {
    float r; asm("cvt.rna.tf32.f32 %0, %1;" : "=f"(r) : "f"(x)); return r;
}
__device__ __forceinline__ void cp16(uint32_t dst, const void* src) {
    asm volatile("cp.async.cg.shared.global [%0], [%1], 16;" :: "r"(dst), "l"(src));
}
#define CP_COMMIT() asm volatile("cp.async.commit_group;" ::: "memory")

__device__ __forceinline__ void mma_tf32(float* c, uint4 a, uint2 b) {
    asm("mma.sync.aligned.m16n8k8.row.col.f32.tf32.tf32.f32 "
        "{%0,%1,%2,%3}, {%4,%5,%6,%7}, {%8,%9}, {%0,%1,%2,%3};"
        : "+f"(c[0]), "+f"(c[1]), "+f"(c[2]), "+f"(c[3])
        : "r"(a.x), "r"(a.y), "r"(a.z), "r"(a.w), "r"(b.x), "r"(b.y));
}

// ---------------------------------------------------------------------------
__global__ void zero_kernel() {
    int i = blockIdx.x * blockDim.x + threadIdx.x;
    if (i < K_) g_counts[i] = 0;
}

__global__ void __launch_bounds__(256) cn2_kernel(const float* __restrict__ cb) {
    int warp = (blockIdx.x * blockDim.x + threadIdx.x) >> 5;
    int lane = threadIdx.x & 31;
    if (warp >= K_) return;
    const float4* row = (const float4*)(cb + (size_t)warp * C_);
    float s = 0.f;
#pragma unroll
    for (int i = 0; i < 2; ++i) {
        float4 v = row[lane + i * 32];
        s += v.x * v.x + v.y * v.y + v.z * v.z + v.w * v.w;
    }
#pragma unroll
    for (int o = 16; o; o >>= 1) s += __shfl_xor_sync(0xFFFFFFFFu, s, o);
    if (lane == 0) g_cn2[warp] = s;
}

// z -> A fragments (transpose + tf32 round). Grid (128, 8) x 256 thr.
__global__ void __launch_bounds__(256) splitA_kernel(const float* __restrict__ z) {
    __shared__ float s[32][132];
    const int blk = blockIdx.x;
    const int ch = blockIdx.y;
    const int tid = threadIdx.x;
    const int b = blk >> 3;
    const int hw0 = (blk & 7) * 128;

    for (int idx = tid; idx < 4096; idx += 256) {
        int cl = idx >> 7, nl = idx & 127;
        s[cl][nl] = z[((size_t)(b * C_ + ch * 32 + cl)) * HW_ + hw0 + nl];
    }
    __syncthreads();
#pragma unroll
    for (int r = 0; r < 4; ++r) {
        int o4 = tid + r * 256;
        int lane = o4 & 31, kst = (o4 >> 5) & 3, mi = (o4 >> 7) & 3, wm = o4 >> 9;
        int col = lane & 3, row = lane >> 2;
        int m = wm * 64 + mi * 16 + row;
        int c = kst * 8 + col;
        float4 h;
        h.x = tf32_rn(s[c][m]);
        h.y = tf32_rn(s[c][m + 8]);
        h.z = tf32_rn(s[c + 4][m]);
        h.w = tf32_rn(s[c + 4][m + 8]);
        g_Ah[(blk * 8 + ch) * 1024 + o4] = h;
    }
}

// codebook -> B fragments. Grid (64, 8) x 256 thr.
__global__ void __launch_bounds__(256) splitB_kernel(const float* __restrict__ cb) {
    const int blk = blockIdx.x;
    const int ch = blockIdx.y;
    const int tid = threadIdx.x;
#pragma unroll
    for (int r = 0; r < 8; ++r) {
        int o2 = tid + r * 256;
        int lane = o2 & 31, kst = (o2 >> 5) & 3, ni = (o2 >> 7) & 3, wn = o2 >> 9;
        int q = blk * 128 + wn * 32 + ni * 8 + (lane >> 2);
        int c = ch * 32 + kst * 8 + (lane & 3);
        float2 h;
        h.x = tf32_rn(cb[(size_t)q * C_ + c]);
        h.y = tf32_rn(cb[(size_t)q * C_ + c + 4]);
        g_Bh[(blk * 8 + ch) * 2048 + o2] = h;
    }
}

// ---------------------------------------------------------------------------
// Main: 1-term tf32 mma.sync screening GEMM + argmin (top1 idx + top2 val).
// 128 CTAs x 256 thr (8 warps: wm in {0,1}, wn in {0..3}), warp tile 64x32.
// 4-stage cp.async pipeline, 32KB/stage.
// ---------------------------------------------------------------------------
__global__ void __launch_bounds__(256, 1)
mma_argmin_kernel(float* __restrict__ out_idx_f) {
    extern __shared__ char sm[];
    const uint32_t smb = smem_u32(sm);

    const int tid = threadIdx.x;
    const int lane = tid & 31;
    const int w = tid >> 5;
    const int wm = w >> 2, wn = w & 3;
    const int blk = blockIdx.x;

    auto load_stage = [&](int g) {
        const int p = g & 3;
        const int ch = g & 7, qb = g >> 3;
        const uint32_t st = smb + (uint32_t)p * STAGE_BYTES;
        const float4* pAh = g_Ah + (blk * 8 + ch) * 1024;
        const float2* pBh = g_Bh + (qb * 8 + ch) * 2048;
#pragma unroll
        for (int r = 0; r < 4; ++r) {
            int i = tid + r * 256;
            cp16(st + i * 16,         pAh + i);
            cp16(st + 16384 + i * 16, (const char*)pBh + i * 16);
        }
        CP_COMMIT();
    };

    load_stage(0);
    load_stage(1);
    load_stage(2);

    float rmin[8], rmin2[8];
    int   ridx[8];
#pragma unroll
    for (int s = 0; s < 8; ++s) { rmin[s] = 3.4e38f; rmin2[s] = 3.4e38f; ridx[s] = 0; }

    const uint32_t aBase = (uint32_t)((wm * 16) * 32 + lane);
    const uint32_t bBase = (uint32_t)((wn * 16) * 32 + lane);

    for (int qb = 0; qb < QBLOCKS; ++qb) {
        float acc[4][4][4];
#pragma unroll
        for (int mi = 0; mi < 4; ++mi)
#pragma unroll
            for (int ni = 0; ni < 4; ++ni)
#pragma unroll
                for (int v = 0; v < 4; ++v) acc[mi][ni][v] = 0.f;

        for (int ch = 0; ch < 8; ++ch) {
            const int g = qb * 8 + ch;
            const int rem = NG - 1 - g;
            if (rem >= 2)      asm volatile("cp.async.wait_group 2;" ::: "memory");
            else if (rem == 1) asm volatile("cp.async.wait_group 1;" ::: "memory");
            else               asm volatile("cp.async.wait_group 0;" ::: "memory");
            __syncthreads();

            const int p = g & 3;
            const uint4* sAh = (const uint4*)(sm + (size_t)p * STAGE_BYTES);
            const uint2* sBh = (const uint2*)(sm + (size_t)p * STAGE_BYTES + 16384);

#pragma unroll
            for (int kst = 0; kst < 4; ++kst) {
                uint4 ah[4];
                uint2 bh[4];
#pragma unroll
                for (int mi = 0; mi < 4; ++mi)
                    ah[mi] = sAh[aBase + (mi * 4 + kst) * 32];
#pragma unroll
                for (int ni = 0; ni < 4; ++ni)
                    bh[ni] = sBh[bBase + (ni * 4 + kst) * 32];
#pragma unroll
                for (int mi = 0; mi < 4; ++mi)
#pragma unroll
                    for (int ni = 0; ni < 4; ++ni)
                        mma_tf32(acc[mi][ni], ah[mi], bh[ni]);
            }

            if (g + 3 < NG) load_stage(g + 3);
        }

        // screening epilogue: top-1 (value+idx) and top-2 (value) per m-slot
#pragma unroll
        for (int ni = 0; ni < 4; ++ni) {
            const int q0 = qb * 128 + wn * 32 + ni * 8 + (lane & 3) * 2;
            const float c2a = __ldg(g_cn2 + q0);
            const float c2b = __ldg(g_cn2 + q0 + 1);
#pragma unroll
            for (int mi = 0; mi < 4; ++mi) {
                float d0 = fmaf(-2.f, acc[mi][ni][0], c2a);
                float d1 = fmaf(-2.f, acc[mi][ni][1], c2b);
                float d2 = fmaf(-2.f, acc[mi][ni][2], c2a);
                float d3 = fmaf(-2.f, acc[mi][ni][3], c2b);
                const int lo = mi * 2, hi = mi * 2 + 1;
                if (d0 < rmin[lo]) { rmin2[lo] = rmin[lo]; rmin[lo] = d0; ridx[lo] = q0; }
                else if (d0 < rmin2[lo]) rmin2[lo] = d0;
                if (d1 < rmin[lo]) { rmin2[lo] = rmin[lo]; rmin[lo] = d1; ridx[lo] = q0 + 1; }
                else if (d1 < rmin2[lo]) rmin2[lo] = d1;
                if (d2 < rmin[hi]) { rmin2[hi] = rmin[hi]; rmin[hi] = d2; ridx[hi] = q0; }
                else if (d2 < rmin2[hi]) rmin2[hi] = d2;
                if (d3 < rmin[hi]) { rmin2[hi] = rmin[hi]; rmin[hi] = d3; ridx[hi] = q0 + 1; }
                else if (d3 < rmin2[hi]) rmin2[hi] = d3;
            }
        }
    }

    // Final cross-thread (v1,i1,v2) reduction; tie -> lower index
    __syncthreads();
    float* rv  = (float*)sm;             // [128][4]
    int*   riv = (int*)(sm + 2048);      // [128][4]
    float* rv2 = (float*)(sm + 4096);    // [128][4]
#pragma unroll
    for (int s = 0; s < 8; ++s) {
        float v1 = rmin[s], v2 = rmin2[s];
        int  i1 = ridx[s];
#pragma unroll
        for (int off = 1; off <= 2; off <<= 1) {
            float ov1 = __shfl_xor_sync(0xFFFFFFFFu, v1, off);
            float ov2 = __shfl_xor_sync(0xFFFFFFFFu, v2, off);
            int  oi1 = __shfl_xor_sync(0xFFFFFFFFu, i1, off);
            if (ov1 < v1 || (ov1 == v1 && oi1 < i1)) {
                v2 = fminf(v1, ov2); v1 = ov1; i1 = oi1;
            } else {
                v2 = fminf(ov1, v2);
            }
        }
        if ((lane & 3) == 0) {
            int row = wm * 64 + (s >> 1) * 16 + (lane >> 2) + (s & 1) * 8;
            rv[row * 4 + wn] = v1;
            riv[row * 4 + wn] = i1;
            rv2[row * 4 + wn] = v2;
        }
    }
    __syncthreads();
    if (tid < 128) {
        float v1 = rv[tid * 4];
        int   i1 = riv[tid * 4];
        float v2 = rv2[tid * 4];
#pragma unroll
        for (int t = 1; t < 4; ++t) {
            float ov1 = rv[tid * 4 + t];
            int  oi1 = riv[tid * 4 + t];
            float ov2 = rv2[tid * 4 + t];
            if (ov1 < v1 || (ov1 == v1 && oi1 < i1)) {
                v2 = fminf(v1, ov2); v1 = ov1; i1 = oi1;
            } else {
                v2 = fminf(ov1, v2);
            }
        }
        const int n = blk * 128 + tid;
        g_flag[n] = (v2 - v1 < MARGIN) ? 1 : 0;
        g_indices[n] = i1;
        out_idx_f[n] = (float)i1;
    }
}

// ---------------------------------------------------------------------------
// Rescue: flagged points get a full re-scan with reference fp32 semantics.
// ---------------------------------------------------------------------------
__global__ void __launch_bounds__(256) rescue_kernel(const float* __restrict__ z,
                                                     const float* __restrict__ cb,
                                                     float* __restrict__ out_idx_f) {
    const int n = blockIdx.x;
    if (g_flag[n] == 0) return;

    __shared__ float zrow[256];
    __shared__ float bd[256];
    __shared__ int   bk[256];
    const int t = threadIdx.x;
    const int b = n >> 10, hw = n & 1023;
    zrow[t] = z[((size_t)(b * C_ + t)) * HW_ + hw];
    __syncthreads();

    double zn2d = 0.0;
    for (int c = 0; c < 256; ++c) zn2d += (double)zrow[c] * (double)zrow[c];
    const float zn2 = (float)zn2d;

    const float4* zr4 = (const float4*)zrow;
    float bestd = FLT_MAX;
    int   bestk = 0x7FFFFFFF;
    for (int k = t; k < K_; k += 256) {
        const float4* cr4 = (const float4*)(cb + (size_t)k * C_);
        float a0 = 0.f, a1 = 0.f, a2 = 0.f, a3 = 0.f;
        float b0 = 0.f, b1 = 0.f, b2 = 0.f, b3 = 0.f;
#pragma unroll
        for (int j = 0; j < 64; j += 2) {
            float4 x = cr4[j],     y = zr4[j];
            a0 = fmaf(x.x, y.x, a0); a1 = fmaf(x.y, y.y, a1);
            a2 = fmaf(x.z, y.z, a2); a3 = fmaf(x.w, y.w, a3);
            float4 x2 = cr4[j + 1], y2 = zr4[j + 1];
            b0 = fmaf(x2.x, y2.x, b0); b1 = fmaf(x2.y, y2.y, b1);
            b2 = fmaf(x2.z, y2.z, b2); b3 = fmaf(x2.w, y2.w, b3);
        }
        float dotf = __fadd_rn(__fadd_rn(__fadd_rn(a0, a1), __fadd_rn(a2, a3)),
                               __fadd_rn(__fadd_rn(b0, b1), __fadd_rn(b2, b3)));
        float d = __fsub_rn(__fadd_rn(zn2, __ldg(g_cn2 + k)), 2.0f * dotf);
        if (d < bestd || (d == bestd && k < bestk)) { bestd = d; bestk = k; }
    }
    bd[t] = bestd;
    bk[t] = bestk;
    __syncthreads();
    if (t == 0) {
        float v = bd[0]; int ix = bk[0];
        for (int i = 1; i < 256; ++i) {
            if (bd[i] < v || (bd[i] == v && bk[i] < ix)) { v = bd[i]; ix = bk[i]; }
        }
        g_indices[n] = ix;
        out_idx_f[n] = (float)ix;
    }
}

// ---------------------------------------------------------------------------
__global__ void __launch_bounds__(256) gather_kernel(const float* __restrict__ z,
                                                     const float* __restrict__ cb,
                                                     float* __restrict__ out_q) {
    __shared__ float q[32][257];
    __shared__ int   sidx[32];
    __shared__ float red[256];
    const int t = threadIdx.x;
    const int b = blockIdx.x >> 5;
    const int h = blockIdx.x & 31;
    const int nbase = b * HW_ + h * 32;

    if (t < 32) {
        int idx = g_indices[nbase + t];
        sidx[t] = idx;
        atomicAdd(&g_counts[idx], 1);
    }
    __syncthreads();

    for (int w = 0; w < 32; ++w)
        q[w][t] = cb[(size_t)sidx[w] * C_ + t];
    __syncthreads();

    float lsum = 0.f;
    const int w  = t & 31;
    const int cg = t >> 5;
    const size_t bb = (size_t)b * C_ * HW_ + h * 32 + w;
    for (int c = cg; c < C_; c += 8) {
        const size_t o = bb + (size_t)c * HW_;
        float qv = q[w][c];
        float zv = z[o];
        out_q[o] = qv;
        float dd = zv - qv;
        lsum = fmaf(dd, dd, lsum);
    }

    red[t] = lsum;
    __syncthreads();
    for (int s = 128; s > 0; s >>= 1) {
        if (t < s) red[t] += red[t + s];
        __syncthreads();
    }
    if (t == 0) g_partials[blockIdx.x] = red[0];
}

__global__ void __launch_bounds__(256) finalize_kernel(float* __restrict__ out) {
    __shared__ float red[256];
    const int t = threadIdx.x;

    float s = 0.f;
    for (int i = t; i < 512; i += 256) s += g_partials[i];
    red[t] = s;
    __syncthreads();
    for (int st = 128; st > 0; st >>= 1) {
        if (t < st) red[t] += red[t + st];
        __syncthreads();
    }
    if (t == 0) {
        float loss = red[0] / (float)NC_;
        out[OFF_LVQ] = loss;
        out[OFF_LC]  = loss;
    }
    __syncthreads();

    float e = 0.f;
    for (int k = t; k < K_; k += 256) {
        float p = (float)g_counts[k] * (1.f / (float)N_);
        if (p > 0.f) e += p * logf(p);
    }
    red[t] = e;
    __syncthreads();
    for (int st = 128; st > 0; st >>= 1) {
        if (t < st) red[t] += red[t + st];
        __syncthreads();
    }
    if (t == 0) out[OFF_P] = expf(-red[0]);
}

// ---------------------------------------------------------------------------
extern "C" void kernel_launch(void* const* d_in, const int* in_sizes, int n_in,
                              void* d_out, int out_size) {
    const float* z  = (const float*)d_in[0];
    const float* cb = (const float*)d_in[1];
    float* out = (float*)d_out;

    cudaFuncSetAttribute(mma_argmin_kernel,
                         cudaFuncAttributeMaxDynamicSharedMemorySize, SMEM_MAIN);

    zero_kernel<<<(K_ + 255) / 256, 256>>>();
    cn2_kernel<<<(K_ * 32) / 256, 256>>>(cb);
    splitA_kernel<<<dim3(NBLOCKS, 8), 256>>>(z);
    splitB_kernel<<<dim3(QBLOCKS, 8), 256>>>(cb);
    mma_argmin_kernel<<<NBLOCKS, 256, SMEM_MAIN>>>(out + OFF_IDX);
    rescue_kernel<<<N_, 256>>>(z, cb, out + OFF_IDX);
    gather_kernel<<<B_ * 32, 256>>>(z, cb, out + OFF_Q);
    finalize_kernel<<<1, 256>>>(out);
}

// round 7
// speedup vs baseline: 2.6682x; 2.6682x over previous
#include <cuda_runtime.h>
#include <cuda_fp16.h>
#include <cstdint>
#include <math.h>
#include <float.h>

// Problem constants
#define B_   16
#define C_   256
#define HW_  1024
#define N_   16384
#define K_   8192
#define NC_  4194304

// Output layout
#define OFF_Q    0
#define OFF_IDX  4194304
#define OFF_P    4210688
#define OFF_LVQ  4210689
#define OFF_LC   4210690

#define NBLOCKS   128    // N_/128
#define QBLOCKS   64     // K_/128
#define NG        512    // QBLOCKS*8 chunks of 32 k
#define STAGE_BYTES 16384
#define SMEM_MAIN   65536   // 4 stages
#define MARGIN    0.25f

// Scratch
__device__ uint4  g_Ahf[NBLOCKS * 8 * 512];    // fp16 A fragments, 8MB
__device__ uint2  g_Bhf[QBLOCKS * 8 * 1024];   // fp16 B fragments, 4MB
__device__ float  g_cn2[K_];
__device__ int    g_counts[K_];
__device__ int    g_indices[N_];
__device__ float  g_partials[512];
// rescue machinery
__device__ int    g_nflag;
__device__ int    g_list[N_];
__device__ float  g_zf[N_ * 256];               // 16MB flagged z rows
__device__ float  g_zn2f[N_];
__device__ unsigned long long g_bestkey[N_];

// ---------------------------------------------------------------------------
__device__ __forceinline__ uint32_t smem_u32(const void* p) {
    uint32_t a;
    asm("{ .reg .u64 t; cvta.to.shared.u64 t, %1; cvt.u32.u64 %0, t; }" : "=r"(a) : "l"(p));
    return a;
}
__device__ __forceinline__ uint32_t pack2(float a, float b) {
    __half2 h = __floats2half2_rn(a, b);
    return *reinterpret_cast<uint32_t*>(&h);
}
__device__ __forceinline__ void cp16(uint32_t dst, const void* src) {
    asm volatile("cp.async.cg.shared.global [%0], [%1], 16;" :: "r"(dst), "l"(src));
}
#define CP_COMMIT() asm volatile("cp.async.commit_group;" ::: "memory")

__device__ __forceinline__ void mma_f16(float* c, uint4 a, uint2 b) {
    asm("mma.sync.aligned.m16n8k16.row.col.f32.f16.f16.f32 "
        "{%0,%1,%2,%3}, {%4,%5,%6,%7}, {%8,%9}, {%0,%1,%2,%3};"
        : "+f"(c[0]), "+f"(c[1]), "+f"(c[2]), "+f"(c[3])
        : "r"(a.x), "r"(a.y), "r"(a.z), "r"(a.w), "r"(b.x), "r"(b.y));
}

// ---------------------------------------------------------------------------
__global__ void zero_kernel() {
    int i = blockIdx.x * blockDim.x + threadIdx.x;
    if (i < K_) g_counts[i] = 0;
    if (i == 0) g_nflag = 0;
}

__global__ void __launch_bounds__(256) cn2_kernel(const float* __restrict__ cb) {
    int warp = (blockIdx.x * blockDim.x + threadIdx.x) >> 5;
    int lane = threadIdx.x & 31;
    if (warp >= K_) return;
    const float4* row = (const float4*)(cb + (size_t)warp * C_);
    float s = 0.f;
#pragma unroll
    for (int i = 0; i < 2; ++i) {
        float4 v = row[lane + i * 32];
        s += v.x * v.x + v.y * v.y + v.z * v.z + v.w * v.w;
    }
#pragma unroll
    for (int o = 16; o; o >>= 1) s += __shfl_xor_sync(0xFFFFFFFFu, s, o);
    if (lane == 0) g_cn2[warp] = s;
}

// z -> fp16 A fragments (m16n8k16 layout). Grid (128, 8) x 256 thr.
__global__ void __launch_bounds__(256) splitA_kernel(const float* __restrict__ z) {
    __shared__ float s[32][132];
    const int blk = blockIdx.x;
    const int ch = blockIdx.y;
    const int tid = threadIdx.x;
    const int b = blk >> 3;
    const int hw0 = (blk & 7) * 128;

    for (int idx = tid; idx < 4096; idx += 256) {
        int cl = idx >> 7, nl = idx & 127;
        s[cl][nl] = z[((size_t)(b * C_ + ch * 32 + cl)) * HW_ + hw0 + nl];
    }
    __syncthreads();
#pragma unroll
    for (int r = 0; r < 2; ++r) {
        int o4 = tid + r * 256;                  // 0..511
        int lane = o4 & 31, kst = (o4 >> 5) & 1, mi = (o4 >> 6) & 3, wm = o4 >> 8;
        int m = wm * 64 + mi * 16 + (lane >> 2);
        int c = kst * 16 + (lane & 3) * 2;
        uint4 fr;
        fr.x = pack2(s[c][m],     s[c + 1][m]);
        fr.y = pack2(s[c][m + 8], s[c + 1][m + 8]);
        fr.z = pack2(s[c + 8][m],     s[c + 9][m]);
        fr.w = pack2(s[c + 8][m + 8], s[c + 9][m + 8]);
        g_Ahf[(blk * 8 + ch) * 512 + o4] = fr;
    }
}

// codebook -> fp16 B fragments. Grid (64, 8) x 256 thr.
__global__ void __launch_bounds__(256) splitB_kernel(const float* __restrict__ cb) {
    const int qb = blockIdx.x;
    const int ch = blockIdx.y;
    const int tid = threadIdx.x;
#pragma unroll
    for (int r = 0; r < 4; ++r) {
        int o2 = tid + r * 256;                  // 0..1023
        int lane = o2 & 31, kst = (o2 >> 5) & 1, ni = (o2 >> 6) & 3, wn = o2 >> 8;
        int q = qb * 128 + wn * 32 + ni * 8 + (lane >> 2);
        int k0 = ch * 32 + kst * 16 + (lane & 3) * 2;
        const float* row = cb + (size_t)q * C_;
        uint2 fr;
        fr.x = pack2(row[k0],     row[k0 + 1]);
        fr.y = pack2(row[k0 + 8], row[k0 + 9]);
        g_Bhf[(qb * 8 + ch) * 1024 + o2] = fr;
    }
}

// ---------------------------------------------------------------------------
// Main: fp16 m16n8k16 screening GEMM + argmin (top1 idx + top2 val + flag list).
// 128 CTAs x 256 thr (8 warps: wm{0,1} x wn{0..3}), warp tile 64x32, 4-stage pipe.
// ---------------------------------------------------------------------------
__global__ void __launch_bounds__(256, 1)
mma_argmin_kernel(float* __restrict__ out_idx_f) {
    extern __shared__ char sm[];
    const uint32_t smb = smem_u32(sm);

    const int tid = threadIdx.x;
    const int lane = tid & 31;
    const int w = tid >> 5;
    const int wm = w >> 2, wn = w & 3;
    const int blk = blockIdx.x;

    auto load_stage = [&](int g) {
        const int p = g & 3;
        const int ch = g & 7, qb = g >> 3;
        const uint32_t st = smb + (uint32_t)p * STAGE_BYTES;
        const uint4* pA = g_Ahf + (blk * 8 + ch) * 512;
        const char*  pB = (const char*)(g_Bhf + (qb * 8 + ch) * 1024);
#pragma unroll
        for (int r = 0; r < 2; ++r) {
            int i = tid + r * 256;
            cp16(st + i * 16,        pA + i);
            cp16(st + 8192 + i * 16, pB + i * 16);
        }
        CP_COMMIT();
    };

    load_stage(0);
    load_stage(1);
    load_stage(2);

    float rmin[8], rmin2[8];
    int   ridx[8];
#pragma unroll
    for (int s = 0; s < 8; ++s) { rmin[s] = 3.4e38f; rmin2[s] = 3.4e38f; ridx[s] = 0; }

    const uint32_t aBase = (uint32_t)(wm * 256 + lane);   // uint4 idx
    const uint32_t bBase = (uint32_t)(wn * 256 + lane);   // uint2 idx

    for (int qb = 0; qb < QBLOCKS; ++qb) {
        float acc[4][4][4];
#pragma unroll
        for (int mi = 0; mi < 4; ++mi)
#pragma unroll
            for (int ni = 0; ni < 4; ++ni)
#pragma unroll
                for (int v = 0; v < 4; ++v) acc[mi][ni][v] = 0.f;

        for (int ch = 0; ch < 8; ++ch) {
            const int g = qb * 8 + ch;
            const int rem = NG - 1 - g;
            if (rem >= 2)      asm volatile("cp.async.wait_group 2;" ::: "memory");
            else if (rem == 1) asm volatile("cp.async.wait_group 1;" ::: "memory");
            else               asm volatile("cp.async.wait_group 0;" ::: "memory");
            __syncthreads();

            const int p = g & 3;
            const uint4* sA = (const uint4*)(sm + (size_t)p * STAGE_BYTES);
            const uint2* sB = (const uint2*)(sm + (size_t)p * STAGE_BYTES + 8192);

#pragma unroll
            for (int kst = 0; kst < 2; ++kst) {
                uint4 ah[4];
                uint2 bh[4];
#pragma unroll
                for (int mi = 0; mi < 4; ++mi)
                    ah[mi] = sA[aBase + mi * 64 + kst * 32];
#pragma unroll
                for (int ni = 0; ni < 4; ++ni)
                    bh[ni] = sB[bBase + ni * 64 + kst * 32];
#pragma unroll
                for (int mi = 0; mi < 4; ++mi)
#pragma unroll
                    for (int ni = 0; ni < 4; ++ni)
                        mma_f16(acc[mi][ni], ah[mi], bh[ni]);
            }

            if (g + 3 < NG) load_stage(g + 3);
        }

        // screening epilogue
#pragma unroll
        for (int ni = 0; ni < 4; ++ni) {
            const int q0 = qb * 128 + wn * 32 + ni * 8 + (lane & 3) * 2;
            const float c2a = __ldg(g_cn2 + q0);
            const float c2b = __ldg(g_cn2 + q0 + 1);
#pragma unroll
            for (int mi = 0; mi < 4; ++mi) {
                float d0 = fmaf(-2.f, acc[mi][ni][0], c2a);
                float d1 = fmaf(-2.f, acc[mi][ni][1], c2b);
                float d2 = fmaf(-2.f, acc[mi][ni][2], c2a);
                float d3 = fmaf(-2.f, acc[mi][ni][3], c2b);
                const int lo = mi * 2, hi = mi * 2 + 1;
                if (d0 < rmin[lo]) { rmin2[lo] = rmin[lo]; rmin[lo] = d0; ridx[lo] = q0; }
                else if (d0 < rmin2[lo]) rmin2[lo] = d0;
                if (d1 < rmin[lo]) { rmin2[lo] = rmin[lo]; rmin[lo] = d1; ridx[lo] = q0 + 1; }
                else if (d1 < rmin2[lo]) rmin2[lo] = d1;
                if (d2 < rmin[hi]) { rmin2[hi] = rmin[hi]; rmin[hi] = d2; ridx[hi] = q0; }
                else if (d2 < rmin2[hi]) rmin2[hi] = d2;
                if (d3 < rmin[hi]) { rmin2[hi] = rmin[hi]; rmin[hi] = d3; ridx[hi] = q0 + 1; }
                else if (d3 < rmin2[hi]) rmin2[hi] = d3;
            }
        }
    }

    // Final cross-thread (v1,i1,v2) reduction; tie -> lower index
    __syncthreads();
    float* rv  = (float*)sm;             // [128][4]
    int*   riv = (int*)(sm + 2048);      // [128][4]
    float* rv2 = (float*)(sm + 4096);    // [128][4]
#pragma unroll
    for (int s = 0; s < 8; ++s) {
        float v1 = rmin[s], v2 = rmin2[s];
        int  i1 = ridx[s];
#pragma unroll
        for (int off = 1; off <= 2; off <<= 1) {
            float ov1 = __shfl_xor_sync(0xFFFFFFFFu, v1, off);
            float ov2 = __shfl_xor_sync(0xFFFFFFFFu, v2, off);
            int  oi1 = __shfl_xor_sync(0xFFFFFFFFu, i1, off);
            if (ov1 < v1 || (ov1 == v1 && oi1 < i1)) {
                v2 = fminf(v1, ov2); v1 = ov1; i1 = oi1;
            } else {
                v2 = fminf(ov1, v2);
            }
        }
        if ((lane & 3) == 0) {
            int row = wm * 64 + (s >> 1) * 16 + (lane >> 2) + (s & 1) * 8;
            rv[row * 4 + wn] = v1;
            riv[row * 4 + wn] = i1;
            rv2[row * 4 + wn] = v2;
        }
    }
    __syncthreads();
    if (tid < 128) {
        float v1 = rv[tid * 4];
        int   i1 = riv[tid * 4];
        float v2 = rv2[tid * 4];
#pragma unroll
        for (int t = 1; t < 4; ++t) {
            float ov1 = rv[tid * 4 + t];
            int  oi1 = riv[tid * 4 + t];
            float ov2 = rv2[tid * 4 + t];
            if (ov1 < v1 || (ov1 == v1 && oi1 < i1)) {
                v2 = fminf(v1, ov2); v1 = ov1; i1 = oi1;
            } else {
                v2 = fminf(ov1, v2);
            }
        }
        const int n = blk * 128 + tid;
        g_indices[n] = i1;
        out_idx_f[n] = (float)i1;
        if (v2 - v1 < MARGIN) {
            int pos = atomicAdd(&g_nflag, 1);
            g_list[pos] = n;
        }
    }
}

// ---------------------------------------------------------------------------
// Compact: copy flagged z rows + fp64 norms, init bestkeys. Grid 128 x 256.
// ---------------------------------------------------------------------------
__global__ void __launch_bounds__(256) compact_kernel(const float* __restrict__ z) {
    __shared__ double rd[256];
    const int t = threadIdx.x;
    const int F = g_nflag;
    for (int f = blockIdx.x; f < F; f += 128) {
        const int n = g_list[f];
        const int b = n >> 10, hw = n & 1023;
        float v = z[((size_t)(b * C_ + t)) * HW_ + hw];
        g_zf[(size_t)f * 256 + t] = v;
        rd[t] = (double)v * (double)v;
        __syncthreads();
        for (int s = 128; s > 0; s >>= 1) {
            if (t < s) rd[t] += rd[t + s];
            __syncthreads();
        }
        if (t == 0) {
            g_zn2f[f] = (float)rd[0];
            g_bestkey[f] = ~0ull;
        }
        __syncthreads();
    }
}

// ---------------------------------------------------------------------------
// Rescue: exact re-scan for flagged points, batched 32 pts x 1024-code slice.
// Grid 1024 (128 tile-stride x 8 slices), 256 thr (8 pt-groups x 32 code lanes).
// ---------------------------------------------------------------------------
__global__ void __launch_bounds__(256) rescue_kernel(const float* __restrict__ cb) {
    const int F = g_nflag;
    if (F == 0) return;
    const int slice = blockIdx.x & 7;
    const int tid = threadIdx.x;
    const int pg = tid >> 5, cl = tid & 31;

    __shared__ float zt[32][260];
    __shared__ float zn2s[32];

    for (int tile = blockIdx.x >> 3; tile * 32 < F; tile += 128) {
        __syncthreads();
        for (int i = tid; i < 8192; i += 256) {
            int p = i >> 8, c = i & 255;
            int f = tile * 32 + p; if (f >= F) f = tile * 32;
            zt[p][c] = g_zf[(size_t)f * 256 + c];
        }
        if (tid < 32) {
            int f = tile * 32 + tid; if (f >= F) f = tile * 32;
            zn2s[tid] = g_zn2f[f];
        }
        __syncthreads();

        const float4* z0 = (const float4*)&zt[pg * 4 + 0][0];
        const float4* z1 = (const float4*)&zt[pg * 4 + 1][0];
        const float4* z2 = (const float4*)&zt[pg * 4 + 2][0];
        const float4* z3 = (const float4*)&zt[pg * 4 + 3][0];

        unsigned long long bk0 = ~0ull, bk1 = ~0ull, bk2 = ~0ull, bk3 = ~0ull;

        for (int ww = 0; ww < 32; ++ww) {
            const int k = slice * 1024 + ww * 32 + cl;
            const float4* cbr = (const float4*)(cb + (size_t)k * C_);
            float4 a0 = {0,0,0,0}, a1 = {0,0,0,0}, a2 = {0,0,0,0}, a3 = {0,0,0,0};
#pragma unroll 4
            for (int j = 0; j < 64; ++j) {
                float4 cv = __ldg(cbr + j);
                float4 x0 = z0[j], x1 = z1[j], x2 = z2[j], x3 = z3[j];
                a0.x = fmaf(cv.x, x0.x, a0.x); a0.y = fmaf(cv.y, x0.y, a0.y);
                a0.z = fmaf(cv.z, x0.z, a0.z); a0.w = fmaf(cv.w, x0.w, a0.w);
                a1.x = fmaf(cv.x, x1.x, a1.x); a1.y = fmaf(cv.y, x1.y, a1.y);
                a1.z = fmaf(cv.z, x1.z, a1.z); a1.w = fmaf(cv.w, x1.w, a1.w);
                a2.x = fmaf(cv.x, x2.x, a2.x); a2.y = fmaf(cv.y, x2.y, a2.y);
                a2.z = fmaf(cv.z, x2.z, a2.z); a2.w = fmaf(cv.w, x2.w, a2.w);
                a3.x = fmaf(cv.x, x3.x, a3.x); a3.y = fmaf(cv.y, x3.y, a3.y);
                a3.z = fmaf(cv.z, x3.z, a3.z); a3.w = fmaf(cv.w, x3.w, a3.w);
            }
            const float c2 = __ldg(g_cn2 + k);
            float dp0 = __fadd_rn(__fadd_rn(a0.x, a0.y), __fadd_rn(a0.z, a0.w));
            float dp1 = __fadd_rn(__fadd_rn(a1.x, a1.y), __fadd_rn(a1.z, a1.w));
            float dp2 = __fadd_rn(__fadd_rn(a2.x, a2.y), __fadd_rn(a2.z, a2.w));
            float dp3 = __fadd_rn(__fadd_rn(a3.x, a3.y), __fadd_rn(a3.z, a3.w));
            float d0 = __fsub_rn(__fadd_rn(zn2s[pg * 4 + 0], c2), 2.0f * dp0);
            float d1 = __fsub_rn(__fadd_rn(zn2s[pg * 4 + 1], c2), 2.0f * dp1);
            float d2 = __fsub_rn(__fadd_rn(zn2s[pg * 4 + 2], c2), 2.0f * dp2);
            float d3 = __fsub_rn(__fadd_rn(zn2s[pg * 4 + 3], c2), 2.0f * dp3);
            unsigned long long k0 = ((unsigned long long)__float_as_uint(d0) << 32) | (unsigned)k;
            unsigned long long k1 = ((unsigned long long)__float_as_uint(d1) << 32) | (unsigned)k;
            unsigned long long k2 = ((unsigned long long)__float_as_uint(d2) << 32) | (unsigned)k;
            unsigned long long k3 = ((unsigned long long)__float_as_uint(d3) << 32) | (unsigned)k;
            if (k0 < bk0) bk0 = k0;
            if (k1 < bk1) bk1 = k1;
            if (k2 < bk2) bk2 = k2;
            if (k3 < bk3) bk3 = k3;
        }
        int fb = tile * 32 + pg * 4;
        if (fb + 0 < F) atomicMin(&g_bestkey[fb + 0], bk0);
        if (fb + 1 < F) atomicMin(&g_bestkey[fb + 1], bk1);
        if (fb + 2 < F) atomicMin(&g_bestkey[fb + 2], bk2);
        if (fb + 3 < F) atomicMin(&g_bestkey[fb + 3], bk3);
    }
}

__global__ void __launch_bounds__(256) writeback_kernel(float* __restrict__ out_idx_f) {
    const int f = blockIdx.x * 256 + threadIdx.x;
    if (f >= g_nflag) return;
    unsigned long long key = g_bestkey[f];
    int idx = (int)(unsigned)(key & 0xFFFFFFFFull);
    int n = g_list[f];
    g_indices[n] = idx;
    out_idx_f[n] = (float)idx;
}

// ---------------------------------------------------------------------------
__global__ void __launch_bounds__(256) gather_kernel(const float* __restrict__ z,
                                                     const float* __restrict__ cb,
                                                     float* __restrict__ out_q) {
    __shared__ float q[32][257];
    __shared__ int   sidx[32];
    __shared__ float red[256];
    const int t = threadIdx.x;
    const int b = blockIdx.x >> 5;
    const int h = blockIdx.x & 31;
    const int nbase = b * HW_ + h * 32;

    if (t < 32) {
        int idx = g_indices[nbase + t];
        sidx[t] = idx;
        atomicAdd(&g_counts[idx], 1);
    }
    __syncthreads();

    for (int w = 0; w < 32; ++w)
        q[w][t] = cb[(size_t)sidx[w] * C_ + t];
    __syncthreads();

    float lsum = 0.f;
    const int w  = t & 31;
    const int cg = t >> 5;
    const size_t bb = (size_t)b * C_ * HW_ + h * 32 + w;
    for (int c = cg; c < C_; c += 8) {
        const size_t o = bb + (size_t)c * HW_;
        float qv = q[w][c];
        float zv = z[o];
        out_q[o] = qv;
        float dd = zv - qv;
        lsum = fmaf(dd, dd, lsum);
    }

    red[t] = lsum;
    __syncthreads();
    for (int s = 128; s > 0; s >>= 1) {
        if (t < s) red[t] += red[t + s];
        __syncthreads();
    }
    if (t == 0) g_partials[blockIdx.x] = red[0];
}

__global__ void __launch_bounds__(256) finalize_kernel(float* __restrict__ out) {
    __shared__ float red[256];
    const int t = threadIdx.x;

    float s = 0.f;
    for (int i = t; i < 512; i += 256) s += g_partials[i];
    red[t] = s;
    __syncthreads();
    for (int st = 128; st > 0; st >>= 1) {
        if (t < st) red[t] += red[t + st];
        __syncthreads();
    }
    if (t == 0) {
        float loss = red[0] / (float)NC_;
        out[OFF_LVQ] = loss;
        out[OFF_LC]  = loss;
    }
    __syncthreads();

    float e = 0.f;
    for (int k = t; k < K_; k += 256) {
        float p = (float)g_counts[k] * (1.f / (float)N_);
        if (p > 0.f) e += p * logf(p);
    }
    red[t] = e;
    __syncthreads();
    for (int st = 128; st > 0; st >>= 1) {
        if (t < st) red[t] += red[t + st];
        __syncthreads();
    }
    if (t == 0) out[OFF_P] = expf(-red[0]);
}

// ---------------------------------------------------------------------------
extern "C" void kernel_launch(void* const* d_in, const int* in_sizes, int n_in,
                              void* d_out, int out_size) {
    const float* z  = (const float*)d_in[0];
    const float* cb = (const float*)d_in[1];
    float* out = (float*)d_out;

    cudaFuncSetAttribute(mma_argmin_kernel,
                         cudaFuncAttributeMaxDynamicSharedMemorySize, SMEM_MAIN);

    zero_kernel<<<(K_ + 255) / 256, 256>>>();
    cn2_kernel<<<(K_ * 32) / 256, 256>>>(cb);
    splitA_kernel<<<dim3(NBLOCKS, 8), 256>>>(z);
    splitB_kernel<<<dim3(QBLOCKS, 8), 256>>>(cb);
    mma_argmin_kernel<<<NBLOCKS, 256, SMEM_MAIN>>>(out + OFF_IDX);
    compact_kernel<<<128, 256>>>(z);
    rescue_kernel<<<1024, 256>>>(cb);
    writeback_kernel<<<64, 256>>>(out + OFF_IDX);
    gather_kernel<<<B_ * 32, 256>>>(z, cb, out + OFF_Q);
    finalize_kernel<<<1, 256>>>(out);
}

// round 8
// speedup vs baseline: 2.6815x; 1.0050x over previous
#include <cuda_runtime.h>
#include <cuda_fp16.h>
#include <cstdint>
#include <math.h>
#include <float.h>

// Problem constants
#define B_   16
#define C_   256
#define HW_  1024
#define N_   16384
#define K_   8192
#define NC_  4194304

// Output layout
#define OFF_Q    0
#define OFF_IDX  4194304
#define OFF_P    4210688
#define OFF_LVQ  4210689
#define OFF_LC   4210690

#define NBLOCKS   128    // N_/128
#define QBLOCKS   64     // K_/128
#define NG        512    // QBLOCKS*8 chunks of 32 k
#define A_BYTES   65536  // resident A tile (fp16 fragments)
#define BSTAGE    8192
#define SMEM_MAIN (A_BYTES + 4 * BSTAGE)   // 98304
#define MARGIN    0.12f

// Scratch
__device__ uint4  g_Ahf[NBLOCKS * 8 * 512];    // fp16 A fragments, 8MB
__device__ uint2  g_Bhf[QBLOCKS * 8 * 1024];   // fp16 B fragments, 4MB
__device__ float  g_cn2[K_];
__device__ int    g_counts[K_];
__device__ int    g_indices[N_];
__device__ float  g_partials[512];
// rescue machinery
__device__ int    g_nflag;
__device__ int    g_list[N_];
__device__ float  g_zf[N_ * 256];
__device__ float  g_zn2f[N_];
__device__ unsigned long long g_bestkey[N_];

// ---------------------------------------------------------------------------
__device__ __forceinline__ uint32_t smem_u32(const void* p) {
    uint32_t a;
    asm("{ .reg .u64 t; cvta.to.shared.u64 t, %1; cvt.u32.u64 %0, t; }" : "=r"(a) : "l"(p));
    return a;
}
__device__ __forceinline__ uint32_t pack2(float a, float b) {
    __half2 h = __floats2half2_rn(a, b);
    return *reinterpret_cast<uint32_t*>(&h);
}
__device__ __forceinline__ void cp16(uint32_t dst, const void* src) {
    asm volatile("cp.async.cg.shared.global [%0], [%1], 16;" :: "r"(dst), "l"(src));
}
#define CP_COMMIT() asm volatile("cp.async.commit_group;" ::: "memory")

__device__ __forceinline__ void mma_f16(float* c, uint4 a, uint2 b) {
    asm("mma.sync.aligned.m16n8k16.row.col.f32.f16.f16.f32 "
        "{%0,%1,%2,%3}, {%4,%5,%6,%7}, {%8,%9}, {%0,%1,%2,%3};"
        : "+f"(c[0]), "+f"(c[1]), "+f"(c[2]), "+f"(c[3])
        : "r"(a.x), "r"(a.y), "r"(a.z), "r"(a.w), "r"(b.x), "r"(b.y));
}

// ---------------------------------------------------------------------------
// cn2 + zero counts + reset flag counter (fused)
__global__ void __launch_bounds__(256) cn2_kernel(const float* __restrict__ cb) {
    const int gid = blockIdx.x * blockDim.x + threadIdx.x;
    if (gid < K_) g_counts[gid] = 0;
    if (gid == 0) g_nflag = 0;
    int warp = gid >> 5;
    int lane = threadIdx.x & 31;
    if (warp >= K_) return;
    const float4* row = (const float4*)(cb + (size_t)warp * C_);
    float s = 0.f;
#pragma unroll
    for (int i = 0; i < 2; ++i) {
        float4 v = row[lane + i * 32];
        s += v.x * v.x + v.y * v.y + v.z * v.z + v.w * v.w;
    }
#pragma unroll
    for (int o = 16; o; o >>= 1) s += __shfl_xor_sync(0xFFFFFFFFu, s, o);
    if (lane == 0) g_cn2[warp] = s;
}

// z -> fp16 A fragments (m16n8k16 layout). Grid (128, 8) x 256 thr.
__global__ void __launch_bounds__(256) splitA_kernel(const float* __restrict__ z) {
    __shared__ float s[32][132];
    const int blk = blockIdx.x;
    const int ch = blockIdx.y;
    const int tid = threadIdx.x;
    const int b = blk >> 3;
    const int hw0 = (blk & 7) * 128;

    for (int idx = tid; idx < 4096; idx += 256) {
        int cl = idx >> 7, nl = idx & 127;
        s[cl][nl] = z[((size_t)(b * C_ + ch * 32 + cl)) * HW_ + hw0 + nl];
    }
    __syncthreads();
#pragma unroll
    for (int r = 0; r < 2; ++r) {
        int o4 = tid + r * 256;
        int lane = o4 & 31, kst = (o4 >> 5) & 1, mi = (o4 >> 6) & 3, wm = o4 >> 8;
        int m = wm * 64 + mi * 16 + (lane >> 2);
        int c = kst * 16 + (lane & 3) * 2;
        uint4 fr;
        fr.x = pack2(s[c][m],     s[c + 1][m]);
        fr.y = pack2(s[c][m + 8], s[c + 1][m + 8]);
        fr.z = pack2(s[c + 8][m],     s[c + 9][m]);
        fr.w = pack2(s[c + 8][m + 8], s[c + 9][m + 8]);
        g_Ahf[(blk * 8 + ch) * 512 + o4] = fr;
    }
}

// codebook -> fp16 B fragments. Grid (64, 8) x 256 thr.
__global__ void __launch_bounds__(256) splitB_kernel(const float* __restrict__ cb) {
    const int qb = blockIdx.x;
    const int ch = blockIdx.y;
    const int tid = threadIdx.x;
#pragma unroll
    for (int r = 0; r < 4; ++r) {
        int o2 = tid + r * 256;
        int lane = o2 & 31, kst = (o2 >> 5) & 1, ni = (o2 >> 6) & 3, wn = o2 >> 8;
        int q = qb * 128 + wn * 32 + ni * 8 + (lane >> 2);
        int k0 = ch * 32 + kst * 16 + (lane & 3) * 2;
        const float* row = cb + (size_t)q * C_;
        uint2 fr;
        fr.x = pack2(row[k0],     row[k0 + 1]);
        fr.y = pack2(row[k0 + 8], row[k0 + 9]);
        g_Bhf[(qb * 8 + ch) * 1024 + o2] = fr;
    }
}

// ---------------------------------------------------------------------------
// Main: fp16 m16n8k16 screening GEMM + argmin. A resident in SMEM (64KB),
// B 4-stage cp.async pipeline (8KB/stage). 128 CTAs x 256 thr.
// ---------------------------------------------------------------------------
__global__ void __launch_bounds__(256, 1)
mma_argmin_kernel(float* __restrict__ out_idx_f) {
    extern __shared__ char sm[];
    const uint32_t smb = smem_u32(sm);

    const int tid = threadIdx.x;
    const int lane = tid & 31;
    const int w = tid >> 5;
    const int wm = w >> 2, wn = w & 3;
    const int blk = blockIdx.x;

    // Resident A: full 128x256 fp16 tile (4096 uint4), one group
    {
        const uint4* pA = g_Ahf + blk * 8 * 512;
#pragma unroll
        for (int r = 0; r < 16; ++r) {
            int i = tid + r * 256;
            cp16(smb + i * 16, pA + i);
        }
        CP_COMMIT();
    }

    auto load_stageB = [&](int g) {
        const int p = g & 3;
        const int ch = g & 7, qb = g >> 3;
        const uint32_t st = smb + A_BYTES + (uint32_t)p * BSTAGE;
        const char* pB = (const char*)(g_Bhf + (qb * 8 + ch) * 1024);
#pragma unroll
        for (int r = 0; r < 2; ++r) {
            int i = tid + r * 256;
            cp16(st + i * 16, pB + i * 16);
        }
        CP_COMMIT();
    };

    load_stageB(0);
    load_stageB(1);
    load_stageB(2);

    float rmin[8], rmin2[8];
    int   ridx[8];
#pragma unroll
    for (int s = 0; s < 8; ++s) { rmin[s] = 3.4e38f; rmin2[s] = 3.4e38f; ridx[s] = 0; }

    const uint32_t aBase = (uint32_t)(wm * 256 + lane);   // uint4 idx within chunk
    const uint32_t bBase = (uint32_t)(wn * 256 + lane);   // uint2 idx

    const uint4* sA = (const uint4*)sm;

    for (int qb = 0; qb < QBLOCKS; ++qb) {
        float acc[4][4][4];
#pragma unroll
        for (int mi = 0; mi < 4; ++mi)
#pragma unroll
            for (int ni = 0; ni < 4; ++ni)
#pragma unroll
                for (int v = 0; v < 4; ++v) acc[mi][ni][v] = 0.f;

        for (int ch = 0; ch < 8; ++ch) {
            const int g = qb * 8 + ch;
            const int rem = NG - 1 - g;
            if (rem >= 2)      asm volatile("cp.async.wait_group 2;" ::: "memory");
            else if (rem == 1) asm volatile("cp.async.wait_group 1;" ::: "memory");
            else               asm volatile("cp.async.wait_group 0;" ::: "memory");
            __syncthreads();

            const int p = g & 3;
            const uint4* sAc = sA + ch * 512;
            const uint2* sB = (const uint2*)(sm + A_BYTES + (size_t)p * BSTAGE);

#pragma unroll
            for (int kst = 0; kst < 2; ++kst) {
                uint4 ah[4];
                uint2 bh[4];
#pragma unroll
                for (int mi = 0; mi < 4; ++mi)
                    ah[mi] = sAc[aBase + mi * 64 + kst * 32];
#pragma unroll
                for (int ni = 0; ni < 4; ++ni)
                    bh[ni] = sB[bBase + ni * 64 + kst * 32];
#pragma unroll
                for (int mi = 0; mi < 4; ++mi)
#pragma unroll
                    for (int ni = 0; ni < 4; ++ni)
                        mma_f16(acc[mi][ni], ah[mi], bh[ni]);
            }

            if (g + 3 < NG) load_stageB(g + 3);
        }

        // screening epilogue
#pragma unroll
        for (int ni = 0; ni < 4; ++ni) {
            const int q0 = qb * 128 + wn * 32 + ni * 8 + (lane & 3) * 2;
            const float c2a = __ldg(g_cn2 + q0);
            const float c2b = __ldg(g_cn2 + q0 + 1);
#pragma unroll
            for (int mi = 0; mi < 4; ++mi) {
                float d0 = fmaf(-2.f, acc[mi][ni][0], c2a);
                float d1 = fmaf(-2.f, acc[mi][ni][1], c2b);
                float d2 = fmaf(-2.f, acc[mi][ni][2], c2a);
                float d3 = fmaf(-2.f, acc[mi][ni][3], c2b);
                const int lo = mi * 2, hi = mi * 2 + 1;
                if (d0 < rmin[lo]) { rmin2[lo] = rmin[lo]; rmin[lo] = d0; ridx[lo] = q0; }
                else if (d0 < rmin2[lo]) rmin2[lo] = d0;
                if (d1 < rmin[lo]) { rmin2[lo] = rmin[lo]; rmin[lo] = d1; ridx[lo] = q0 + 1; }
                else if (d1 < rmin2[lo]) rmin2[lo] = d1;
                if (d2 < rmin[hi]) { rmin2[hi] = rmin[hi]; rmin[hi] = d2; ridx[hi] = q0; }
                else if (d2 < rmin2[hi]) rmin2[hi] = d2;
                if (d3 < rmin[hi]) { rmin2[hi] = rmin[hi]; rmin[hi] = d3; ridx[hi] = q0 + 1; }
                else if (d3 < rmin2[hi]) rmin2[hi] = d3;
            }
        }
    }

    // Final cross-thread (v1,i1,v2) reduction; tie -> lower index
    __syncthreads();
    float* rv  = (float*)sm;             // [128][4] (A region dead now)
    int*   riv = (int*)(sm + 2048);
    float* rv2 = (float*)(sm + 4096);
#pragma unroll
    for (int s = 0; s < 8; ++s) {
        float v1 = rmin[s], v2 = rmin2[s];
        int  i1 = ridx[s];
#pragma unroll
        for (int off = 1; off <= 2; off <<= 1) {
            float ov1 = __shfl_xor_sync(0xFFFFFFFFu, v1, off);
            float ov2 = __shfl_xor_sync(0xFFFFFFFFu, v2, off);
            int  oi1 = __shfl_xor_sync(0xFFFFFFFFu, i1, off);
            if (ov1 < v1 || (ov1 == v1 && oi1 < i1)) {
                v2 = fminf(v1, ov2); v1 = ov1; i1 = oi1;
            } else {
                v2 = fminf(ov1, v2);
            }
        }
        if ((lane & 3) == 0) {
            int row = wm * 64 + (s >> 1) * 16 + (lane >> 2) + (s & 1) * 8;
            rv[row * 4 + wn] = v1;
            riv[row * 4 + wn] = i1;
            rv2[row * 4 + wn] = v2;
        }
    }
    __syncthreads();
    if (tid < 128) {
        float v1 = rv[tid * 4];
        int   i1 = riv[tid * 4];
        float v2 = rv2[tid * 4];
#pragma unroll
        for (int t = 1; t < 4; ++t) {
            float ov1 = rv[tid * 4 + t];
            int  oi1 = riv[tid * 4 + t];
            float ov2 = rv2[tid * 4 + t];
            if (ov1 < v1 || (ov1 == v1 && oi1 < i1)) {
                v2 = fminf(v1, ov2); v1 = ov1; i1 = oi1;
            } else {
                v2 = fminf(ov1, v2);
            }
        }
        const int n = blk * 128 + tid;
        g_indices[n] = i1;
        out_idx_f[n] = (float)i1;
        if (v2 - v1 < MARGIN) {
            int pos = atomicAdd(&g_nflag, 1);
            g_list[pos] = n;
        }
    }
}

// ---------------------------------------------------------------------------
__global__ void __launch_bounds__(256) compact_kernel(const float* __restrict__ z) {
    __shared__ double rd[256];
    const int t = threadIdx.x;
    const int F = g_nflag;
    for (int f = blockIdx.x; f < F; f += 128) {
        const int n = g_list[f];
        const int b = n >> 10, hw = n & 1023;
        float v = z[((size_t)(b * C_ + t)) * HW_ + hw];
        g_zf[(size_t)f * 256 + t] = v;
        rd[t] = (double)v * (double)v;
        __syncthreads();
        for (int s = 128; s > 0; s >>= 1) {
            if (t < s) rd[t] += rd[t + s];
            __syncthreads();
        }
        if (t == 0) {
            g_zn2f[f] = (float)rd[0];
            g_bestkey[f] = ~0ull;
        }
        __syncthreads();
    }
}

// ---------------------------------------------------------------------------
// Rescue: exact re-scan, batched 32 pts x 1024-code slice.
// ---------------------------------------------------------------------------
__global__ void __launch_bounds__(256) rescue_kernel(const float* __restrict__ cb) {
    const int F = g_nflag;
    if (F == 0) return;
    const int slice = blockIdx.x & 7;
    const int tid = threadIdx.x;
    const int pg = tid >> 5, cl = tid & 31;

    __shared__ float zt[32][260];
    __shared__ float zn2s[32];

    for (int tile = blockIdx.x >> 3; tile * 32 < F; tile += 128) {
        __syncthreads();
        for (int i = tid; i < 8192; i += 256) {
            int p = i >> 8, c = i & 255;
            int f = tile * 32 + p; if (f >= F) f = tile * 32;
            zt[p][c] = g_zf[(size_t)f * 256 + c];
        }
        if (tid < 32) {
            int f = tile * 32 + tid; if (f >= F) f = tile * 32;
            zn2s[tid] = g_zn2f[f];
        }
        __syncthreads();

        const float4* z0 = (const float4*)&zt[pg * 4 + 0][0];
        const float4* z1 = (const float4*)&zt[pg * 4 + 1][0];
        const float4* z2 = (const float4*)&zt[pg * 4 + 2][0];
        const float4* z3 = (const float4*)&zt[pg * 4 + 3][0];

        unsigned long long bk0 = ~0ull, bk1 = ~0ull, bk2 = ~0ull, bk3 = ~0ull;

        for (int ww = 0; ww < 32; ++ww) {
            const int k = slice * 1024 + ww * 32 + cl;
            const float4* cbr = (const float4*)(cb + (size_t)k * C_);
            float4 a0 = {0,0,0,0}, a1 = {0,0,0,0}, a2 = {0,0,0,0}, a3 = {0,0,0,0};
#pragma unroll 4
            for (int j = 0; j < 64; ++j) {
                float4 cv = __ldg(cbr + j);
                float4 x0 = z0[j], x1 = z1[j], x2 = z2[j], x3 = z3[j];
                a0.x = fmaf(cv.x, x0.x, a0.x); a0.y = fmaf(cv.y, x0.y, a0.y);
                a0.z = fmaf(cv.z, x0.z, a0.z); a0.w = fmaf(cv.w, x0.w, a0.w);
                a1.x = fmaf(cv.x, x1.x, a1.x); a1.y = fmaf(cv.y, x1.y, a1.y);
                a1.z = fmaf(cv.z, x1.z, a1.z); a1.w = fmaf(cv.w, x1.w, a1.w);
                a2.x = fmaf(cv.x, x2.x, a2.x); a2.y = fmaf(cv.y, x2.y, a2.y);
                a2.z = fmaf(cv.z, x2.z, a2.z); a2.w = fmaf(cv.w, x2.w, a2.w);
                a3.x = fmaf(cv.x, x3.x, a3.x); a3.y = fmaf(cv.y, x3.y, a3.y);
                a3.z = fmaf(cv.z, x3.z, a3.z); a3.w = fmaf(cv.w, x3.w, a3.w);
            }
            const float c2 = __ldg(g_cn2 + k);
            float dp0 = __fadd_rn(__fadd_rn(a0.x, a0.y), __fadd_rn(a0.z, a0.w));
            float dp1 = __fadd_rn(__fadd_rn(a1.x, a1.y), __fadd_rn(a1.z, a1.w));
            float dp2 = __fadd_rn(__fadd_rn(a2.x, a2.y), __fadd_rn(a2.z, a2.w));
            float dp3 = __fadd_rn(__fadd_rn(a3.x, a3.y), __fadd_rn(a3.z, a3.w));
            float d0 = __fsub_rn(__fadd_rn(zn2s[pg * 4 + 0], c2), 2.0f * dp0);
            float d1 = __fsub_rn(__fadd_rn(zn2s[pg * 4 + 1], c2), 2.0f * dp1);
            float d2 = __fsub_rn(__fadd_rn(zn2s[pg * 4 + 2], c2), 2.0f * dp2);
            float d3 = __fsub_rn(__fadd_rn(zn2s[pg * 4 + 3], c2), 2.0f * dp3);
            unsigned long long k0 = ((unsigned long long)__float_as_uint(d0) << 32) | (unsigned)k;
            unsigned long long k1 = ((unsigned long long)__float_as_uint(d1) << 32) | (unsigned)k;
            unsigned long long k2 = ((unsigned long long)__float_as_uint(d2) << 32) | (unsigned)k;
            unsigned long long k3 = ((unsigned long long)__float_as_uint(d3) << 32) | (unsigned)k;
            if (k0 < bk0) bk0 = k0;
            if (k1 < bk1) bk1 = k1;
            if (k2 < bk2) bk2 = k2;
            if (k3 < bk3) bk3 = k3;
        }
        int fb = tile * 32 + pg * 4;
        if (fb + 0 < F) atomicMin(&g_bestkey[fb + 0], bk0);
        if (fb + 1 < F) atomicMin(&g_bestkey[fb + 1], bk1);
        if (fb + 2 < F) atomicMin(&g_bestkey[fb + 2], bk2);
        if (fb + 3 < F) atomicMin(&g_bestkey[fb + 3], bk3);
    }
}

__global__ void __launch_bounds__(256) writeback_kernel(float* __restrict__ out_idx_f) {
    const int f = blockIdx.x * 256 + threadIdx.x;
    if (f >= g_nflag) return;
    unsigned long long key = g_bestkey[f];
    int idx = (int)(unsigned)(key & 0xFFFFFFFFull);
    int n = g_list[f];
    g_indices[n] = idx;
    out_idx_f[n] = (float)idx;
}

// ---------------------------------------------------------------------------
__global__ void __launch_bounds__(256) gather_kernel(const float* __restrict__ z,
                                                     const float* __restrict__ cb,
                                                     float* __restrict__ out_q) {
    __shared__ float q[32][257];
    __shared__ int   sidx[32];
    __shared__ float red[256];
    const int t = threadIdx.x;
    const int b = blockIdx.x >> 5;
    const int h = blockIdx.x & 31;
    const int nbase = b * HW_ + h * 32;

    if (t < 32) {
        int idx = g_indices[nbase + t];
        sidx[t] = idx;
        atomicAdd(&g_counts[idx], 1);
    }
    __syncthreads();

    for (int w = 0; w < 32; ++w)
        q[w][t] = cb[(size_t)sidx[w] * C_ + t];
    __syncthreads();

    float lsum = 0.f;
    const int w  = t & 31;
    const int cg = t >> 5;
    const size_t bb = (size_t)b * C_ * HW_ + h * 32 + w;
    for (int c = cg; c < C_; c += 8) {
        const size_t o = bb + (size_t)c * HW_;
        float qv = q[w][c];
        float zv = z[o];
        out_q[o] = qv;
        float dd = zv - qv;
        lsum = fmaf(dd, dd, lsum);
    }

    red[t] = lsum;
    __syncthreads();
    for (int s = 128; s > 0; s >>= 1) {
        if (t < s) red[t] += red[t + s];
        __syncthreads();
    }
    if (t == 0) g_partials[blockIdx.x] = red[0];
}

__global__ void __launch_bounds__(256) finalize_kernel(float* __restrict__ out) {
    __shared__ float red[256];
    const int t = threadIdx.x;

    float s = 0.f;
    for (int i = t; i < 512; i += 256) s += g_partials[i];
    red[t] = s;
    __syncthreads();
    for (int st = 128; st > 0; st >>= 1) {
        if (t < st) red[t] += red[t + st];
        __syncthreads();
    }
    if (t == 0) {
        float loss = red[0] / (float)NC_;
        out[OFF_LVQ] = loss;
        out[OFF_LC]  = loss;
    }
    __syncthreads();

    float e = 0.f;
    for (int k = t; k < K_; k += 256) {
        float p = (float)g_counts[k] * (1.f / (float)N_);
        if (p > 0.f) e += p * logf(p);
    }
    red[t] = e;
    __syncthreads();
    for (int st = 128; st > 0; st >>= 1) {
        if (t < st) red[t] += red[t + st];
        __syncthreads();
    }
    if (t == 0) out[OFF_P] = expf(-red[0]);
}

// ---------------------------------------------------------------------------
extern "C" void kernel_launch(void* const* d_in, const int* in_sizes, int n_in,
                              void* d_out, int out_size) {
    const float* z  = (const float*)d_in[0];
    const float* cb = (const float*)d_in[1];
    float* out = (float*)d_out;

    cudaFuncSetAttribute(mma_argmin_kernel,
                         cudaFuncAttributeMaxDynamicSharedMemorySize, SMEM_MAIN);

    cn2_kernel<<<(K_ * 32) / 256, 256>>>(cb);
    splitA_kernel<<<dim3(NBLOCKS, 8), 256>>>(z);
    splitB_kernel<<<dim3(QBLOCKS, 8), 256>>>(cb);
    mma_argmin_kernel<<<NBLOCKS, 256, SMEM_MAIN>>>(out + OFF_IDX);
    compact_kernel<<<128, 256>>>(z);
    rescue_kernel<<<1024, 256>>>(cb);
    writeback_kernel<<<64, 256>>>(out + OFF_IDX);
    gather_kernel<<<B_ * 32, 256>>>(z, cb, out + OFF_Q);
    finalize_kernel<<<1, 256>>>(out);
}